// round 1
// baseline (speedup 1.0000x reference)
#include <cuda_runtime.h>
#include <cuda_bf16.h>
#include <cstdio>

typedef unsigned long long ull;

// ---------------- constants ----------------
// B=32, S=64, D=256, H=8, E=8, K(topk)=2, F=1024, LATENT=64, HD=32
#define TOK      2048          // B*S = 32*64 (also B*LATENT)
#define DMODEL   256
#define NBIG     16384         // S*D = LATENT*D
#define SPLITK   4
#define KCHUNK   4096          // 16384/4
#define FEXP     1024
#define NEXP     8

// ---------------- scratch (device globals; no allocs allowed) ----------------
__device__ float g_y1 [TOK*DMODEL];
__device__ float g_part[SPLITK*32*NBIG];
__device__ float g_lat[TOK*DMODEL];
__device__ float g_q  [TOK*DMODEL];
__device__ float g_k  [TOK*DMODEL];
__device__ float g_v  [TOK*DMODEL];
__device__ float g_ao [TOK*DMODEL];
__device__ float g_x2 [TOK*DMODEL];
__device__ float g_y2 [TOK*DMODEL];
__device__ float g_topv[TOK*2];
__device__ int   g_cnt[NEXP];
__device__ int   g_list[NEXP*TOK];
__device__ float g_h1 [NEXP*TOK*FEXP];   // 64 MB
__device__ float g_h2 [NEXP*TOK*FEXP];   // 64 MB
__device__ float g_eo [2*TOK*DMODEL];

// ---------------- packed fp32x2 helpers ----------------
__device__ __forceinline__ void ffma2(ull& d, ull a, ull b) {
    asm("fma.rn.f32x2 %0, %1, %2, %0;" : "+l"(d) : "l"(a), "l"(b));
}
__device__ __forceinline__ ull dup2(float x) {
    ull r; unsigned xi = __float_as_uint(x);
    asm("mov.b64 %0, {%1, %1};" : "=l"(r) : "r"(xi));
    return r;
}
__device__ __forceinline__ float2 unpack2(ull a) {
    unsigned lo, hi;
    asm("mov.b64 {%0, %1}, %2;" : "=r"(lo), "=r"(hi) : "l"(a));
    float2 r; r.x = __uint_as_float(lo); r.y = __uint_as_float(hi);
    return r;
}

// ---------------- rmsnorm (one block per row of 256) ----------------
__global__ void rmsnorm_kernel(const float* __restrict__ in, const float* __restrict__ w,
                               float* __restrict__ out) {
    int row = blockIdx.x, t = threadIdx.x;
    float v = in[(size_t)row*DMODEL + t];
    float ss = v*v;
    #pragma unroll
    for (int o = 16; o > 0; o >>= 1) ss += __shfl_xor_sync(0xffffffffu, ss, o);
    __shared__ float ws[8];
    if ((t & 31) == 0) ws[t >> 5] = ss;
    __syncthreads();
    float tot = 0.f;
    #pragma unroll
    for (int i = 0; i < 8; i++) tot += ws[i];
    float sc = rsqrtf(tot * (1.0f/256.0f) + 1e-5f);
    out[(size_t)row*DMODEL + t] = v * sc * w[t];
}

// ---------------- Wl GEMM: [32,16384] @ [16384,16384], split-K=4 ----------------
// block: 256 thr. tile: all 32 rows x 128 cols. thread: 4 rows x 4 cols via f32x2.
__global__ void wl_gemm(const float* __restrict__ A, const float* __restrict__ W,
                        float* __restrict__ part) {
    __shared__ __align__(16) float As[32*34];     // [k][m], stride 34
    __shared__ __align__(16) float Bs[32*128];    // [k][n]
    int tid = threadIdx.x;
    int n0 = blockIdx.x * 128;
    int kbase = blockIdx.y * KCHUNK;
    int ng = tid & 31, mg = tid >> 5;
    ull acc[2][4];
    #pragma unroll
    for (int i = 0; i < 2; i++)
        #pragma unroll
        for (int j = 0; j < 4; j++) acc[i][j] = 0ULL;

    for (int kt = 0; kt < KCHUNK; kt += 32) {
        __syncthreads();
        {   // stage A tile 32k x 32m (coalesced along k)
            int kk = tid & 31, r0 = tid >> 5;
            #pragma unroll
            for (int p = 0; p < 4; p++) {
                int r = r0 + p*8;
                As[kk*34 + r] = A[(size_t)r*NBIG + kbase + kt + kk];
            }
        }
        {   // stage W tile 32k x 128n (coalesced along n)
            int nn = tid & 127, kx = tid >> 7;
            #pragma unroll
            for (int p = 0; p < 16; p++) {
                int kk = kx + p*2;
                Bs[kk*128 + nn] = W[(size_t)(kbase + kt + kk)*NBIG + n0 + nn];
            }
        }
        __syncthreads();
        #pragma unroll
        for (int k = 0; k < 32; k++) {
            ull a0 = *(const ull*)&As[k*34 + mg*4];
            ull a1 = *(const ull*)&As[k*34 + mg*4 + 2];
            float4 b4 = *(const float4*)&Bs[k*128 + ng*4];
            ull b0 = dup2(b4.x), b1 = dup2(b4.y), b2 = dup2(b4.z), b3 = dup2(b4.w);
            ffma2(acc[0][0], a0, b0); ffma2(acc[0][1], a0, b1);
            ffma2(acc[0][2], a0, b2); ffma2(acc[0][3], a0, b3);
            ffma2(acc[1][0], a1, b0); ffma2(acc[1][1], a1, b1);
            ffma2(acc[1][2], a1, b2); ffma2(acc[1][3], a1, b3);
        }
    }
    size_t base = (size_t)blockIdx.y * (32*(size_t)NBIG);
    #pragma unroll
    for (int rp = 0; rp < 2; rp++) {
        #pragma unroll
        for (int c = 0; c < 4; c++) {
            float2 f = unpack2(acc[rp][c]);
            int n = n0 + ng*4 + c;
            int r = mg*4 + rp*2;
            part[base + (size_t)r*NBIG + n]     = f.x;
            part[base + (size_t)(r+1)*NBIG + n] = f.y;
        }
    }
}

__global__ void wl_reduce(const float* __restrict__ part, const float* __restrict__ bl,
                          float* __restrict__ lat) {
    int i = blockIdx.x * 256 + threadIdx.x;       // 0 .. 524287
    float s = bl[i & (NBIG-1)];
    #pragma unroll
    for (int p = 0; p < SPLITK; p++) s += part[(size_t)p*32*NBIG + i];
    lat[i] = s;
}

// ---------------- generic 64x64 tiled GEMM (gather/scatter/expert modes) ----------
// mode 0: C[r] = A[r] @ W (+bias)(+resid)        (gridDim.z==1)
// mode 1: A row gathered via list>>1, C = Cbase + e*TOK*N, row r   (MoE layer 1)
// mode 2: A = Abase + e*TOK*K row r, C likewise                     (MoE layer 2)
// mode 3: A = Abase + e*TOK*K row r, C scattered by list (slot,tok) (MoE layer 3)
__global__ void gemm64(const float* __restrict__ A, const float* __restrict__ W,
                       const float* __restrict__ bias, const float* __restrict__ resid,
                       float* __restrict__ C, int M, int N, int K,
                       const int* __restrict__ list, const int* __restrict__ cntp,
                       int mode, int relu) {
    __shared__ __align__(16) float As[16*66];     // [k][m], stride 66
    __shared__ __align__(16) float Bs[16*64];     // [k][n]
    __shared__ const float* rowp[64];

    int e = blockIdx.z;
    int rows = cntp ? cntp[e] : M;
    int m0 = blockIdx.y * 64;
    if (m0 >= rows) return;
    int n0 = blockIdx.x * 64;
    const float* We = W + (size_t)e * K * N;
    const float* be = bias + (size_t)e * N;
    int tid = threadIdx.x;

    if (tid < 64) {
        int r = m0 + tid;
        const float* p = nullptr;
        if (r < rows) {
            if (mode == 1)       p = A + (size_t)(list[e*TOK + r] >> 1) * K;
            else if (mode == 0)  p = A + (size_t)r * K;
            else                 p = A + ((size_t)e*TOK + r) * K;
        }
        rowp[tid] = p;
    }
    __syncthreads();

    ull acc[2][4];
    #pragma unroll
    for (int i = 0; i < 2; i++)
        #pragma unroll
        for (int j = 0; j < 4; j++) acc[i][j] = 0ULL;
    int tx = tid & 15, ty = tid >> 4;

    for (int k0 = 0; k0 < K; k0 += 16) {
        __syncthreads();
        {
            int kk = tid & 15, r0 = tid >> 4;
            #pragma unroll
            for (int p4 = 0; p4 < 4; p4++) {
                int r = r0 + p4*16;
                const float* p = rowp[r];
                As[kk*66 + r] = p ? p[k0 + kk] : 0.f;
            }
        }
        {
            int nn = tid & 63, kx = tid >> 6;
            #pragma unroll
            for (int p4 = 0; p4 < 4; p4++) {
                int kk = kx + p4*4;
                Bs[kk*64 + nn] = We[(size_t)(k0 + kk)*N + n0 + nn];
            }
        }
        __syncthreads();
        #pragma unroll
        for (int kk = 0; kk < 16; kk++) {
            ull a0 = *(const ull*)&As[kk*66 + ty*4];
            ull a1 = *(const ull*)&As[kk*66 + ty*4 + 2];
            float4 b4 = *(const float4*)&Bs[kk*64 + tx*4];
            ull b0 = dup2(b4.x), b1 = dup2(b4.y), b2 = dup2(b4.z), b3 = dup2(b4.w);
            ffma2(acc[0][0], a0, b0); ffma2(acc[0][1], a0, b1);
            ffma2(acc[0][2], a0, b2); ffma2(acc[0][3], a0, b3);
            ffma2(acc[1][0], a1, b0); ffma2(acc[1][1], a1, b1);
            ffma2(acc[1][2], a1, b2); ffma2(acc[1][3], a1, b3);
        }
    }

    #pragma unroll
    for (int rp = 0; rp < 2; rp++) {
        #pragma unroll
        for (int h2 = 0; h2 < 2; h2++) {
            int r = ty*4 + rp*2 + h2;
            int row = m0 + r;
            if (row >= rows) continue;
            float* crow;
            if (mode == 3) {
                int ent = list[e*TOK + row];
                crow = C + (size_t)(ent & 1)*TOK*N + (size_t)(ent >> 1)*N;
            } else if (mode == 0) {
                crow = C + (size_t)row * N;
            } else {
                crow = C + ((size_t)e*TOK + row) * N;
            }
            #pragma unroll
            for (int c = 0; c < 4; c++) {
                float2 f = unpack2(acc[rp][c]);
                float val = (h2 == 0) ? f.x : f.y;
                int n = n0 + tx*4 + c;
                val += be[n];
                if (resid) val += resid[(size_t)row*N + n];
                if (relu)  val = fmaxf(val, 0.f);
                crow[n] = val;
            }
        }
    }
}

// ---------------- attention: one block per (b,h), 64 threads (one per s) --------
__global__ void attn_kernel(const float* __restrict__ q, const float* __restrict__ k,
                            const float* __restrict__ v, float* __restrict__ ao) {
    int bh = blockIdx.x;
    int b = bh >> 3, h = bh & 7;
    int s = threadIdx.x;               // 0..63
    __shared__ float ks[64][32];
    __shared__ float vs[64][32];
    for (int idx = s; idx < 2048; idx += 64) {
        int l = idx >> 5, d = idx & 31;
        size_t src = (size_t)(b*64 + l)*DMODEL + h*32 + d;
        ks[l][d] = k[src];
        vs[l][d] = v[src];
    }
    __syncthreads();

    float qr[32];
    const float* qp = q + (size_t)(b*64 + s)*DMODEL + h*32;
    #pragma unroll
    for (int d = 0; d < 32; d++) qr[d] = qp[d];

    // RoPE (bug-faithful: imaginary part uses the updated real part)
    #pragma unroll
    for (int i = 0; i < 16; i++) {
        float fr = powf(10000.0f, -(float)i / 16.0f);
        float ang = (float)s * fr;
        float c = cosf(ang), sn = sinf(ang);
        float X = qr[2*i], Y = qr[2*i + 1];
        float nX = X*c - Y*sn;
        float nY = nX*sn + Y*c;
        qr[2*i] = nX; qr[2*i + 1] = nY;
    }

    const float scale = 0.1767766952966369f;   // 1/sqrt(32)
    float sc[64];
    float mx = -1e30f;
    #pragma unroll
    for (int l = 0; l < 64; l++) {
        float p = 0.f;
        #pragma unroll
        for (int d = 0; d < 32; d++) p += qr[d] * ks[l][d];
        p *= scale;
        sc[l] = p;
        mx = fmaxf(mx, p);
    }
    float se = 0.f;
    #pragma unroll
    for (int l = 0; l < 64; l++) { sc[l] = __expf(sc[l] - mx); se += sc[l]; }
    float inv = 1.0f / se;

    float* op = ao + (size_t)(b*64 + s)*DMODEL + h*32;
    #pragma unroll
    for (int d = 0; d < 32; d++) {
        float a = 0.f;
        #pragma unroll
        for (int l = 0; l < 64; l++) a += sc[l] * vs[l][d];
        op[d] = a * inv;
    }
}

// ---------------- router: softmax + top2 + expert list build --------------------
__global__ void zero_cnt_kernel(int* cnt) { if (threadIdx.x < NEXP) cnt[threadIdx.x] = 0; }

__global__ void route_kernel(const float* __restrict__ y2, const float* __restrict__ rw,
                             const float* __restrict__ rb, float* __restrict__ topv,
                             int* __restrict__ cnt, int* __restrict__ list) {
    int tok = blockIdx.x, lane = threadIdx.x;    // 32 threads
    float xv[8];
    #pragma unroll
    for (int j = 0; j < 8; j++) xv[j] = y2[(size_t)tok*DMODEL + j*32 + lane];
    float lg[8];
    #pragma unroll
    for (int e = 0; e < 8; e++) {
        float p = 0.f;
        #pragma unroll
        for (int j = 0; j < 8; j++) p += xv[j] * rw[(j*32 + lane)*NEXP + e];
        #pragma unroll
        for (int o = 16; o > 0; o >>= 1) p += __shfl_xor_sync(0xffffffffu, p, o);
        lg[e] = p;
    }
    if (lane == 0) {
        float mx = -1e30f;
        #pragma unroll
        for (int e = 0; e < 8; e++) { lg[e] += rb[e]; mx = fmaxf(mx, lg[e]); }
        float se = 0.f, pr[8];
        #pragma unroll
        for (int e = 0; e < 8; e++) { pr[e] = __expf(lg[e] - mx); se += pr[e]; }
        float inv = 1.0f / se;
        #pragma unroll
        for (int e = 0; e < 8; e++) pr[e] *= inv;
        int b0 = 0; float v0 = -1.f;
        #pragma unroll
        for (int e = 0; e < 8; e++) if (pr[e] > v0) { v0 = pr[e]; b0 = e; }
        int b1 = -1; float v1 = -1.f;
        #pragma unroll
        for (int e = 0; e < 8; e++) if (e != b0 && pr[e] > v1) { v1 = pr[e]; b1 = e; }
        topv[tok*2 + 0] = v0;
        topv[tok*2 + 1] = v1;
        int p0 = atomicAdd(&cnt[b0], 1); list[b0*TOK + p0] = tok*2;
        int p1 = atomicAdd(&cnt[b1], 1); list[b1*TOK + p1] = tok*2 + 1;
    }
}

// ---------------- final combine: out = x2 + tv0*eo0 + tv1*eo1 -------------------
__global__ void combine_kernel(const float* __restrict__ x2, const float* __restrict__ topv,
                               const float* __restrict__ eo, float* __restrict__ out) {
    int tok = blockIdx.x, d = threadIdx.x;
    size_t i = (size_t)tok*DMODEL + d;
    out[i] = x2[i] + topv[tok*2] * eo[i] + topv[tok*2 + 1] * eo[(size_t)TOK*DMODEL + i];
}

// ---------------- host launcher -------------------------------------------------
extern "C" void kernel_launch(void* const* d_in, const int* in_sizes, int n_in,
                              void* d_out, int out_size) {
    const float* x   = (const float*)d_in[0];
    const float* r1w = (const float*)d_in[1];
    const float* Wl  = (const float*)d_in[2];
    const float* bl  = (const float*)d_in[3];
    const float* Wq  = (const float*)d_in[4];
    const float* bq  = (const float*)d_in[5];
    const float* Wk  = (const float*)d_in[6];
    const float* bk  = (const float*)d_in[7];
    const float* Wv  = (const float*)d_in[8];
    const float* bv  = (const float*)d_in[9];
    const float* Wo  = (const float*)d_in[10];
    const float* bo  = (const float*)d_in[11];
    const float* r2w = (const float*)d_in[12];
    const float* rw  = (const float*)d_in[13];
    const float* rb  = (const float*)d_in[14];
    const float* W1  = (const float*)d_in[15];
    const float* b1  = (const float*)d_in[16];
    const float* Wsx = (const float*)d_in[17];
    const float* bs  = (const float*)d_in[18];
    const float* W2  = (const float*)d_in[19];
    const float* b2  = (const float*)d_in[20];

    float *y1, *part, *lat, *q, *kb, *vb, *ao, *x2, *y2, *topv, *h1, *h2, *eo;
    int *cnt, *list;
    cudaGetSymbolAddress((void**)&y1,   g_y1);
    cudaGetSymbolAddress((void**)&part, g_part);
    cudaGetSymbolAddress((void**)&lat,  g_lat);
    cudaGetSymbolAddress((void**)&q,    g_q);
    cudaGetSymbolAddress((void**)&kb,   g_k);
    cudaGetSymbolAddress((void**)&vb,   g_v);
    cudaGetSymbolAddress((void**)&ao,   g_ao);
    cudaGetSymbolAddress((void**)&x2,   g_x2);
    cudaGetSymbolAddress((void**)&y2,   g_y2);
    cudaGetSymbolAddress((void**)&topv, g_topv);
    cudaGetSymbolAddress((void**)&h1,   g_h1);
    cudaGetSymbolAddress((void**)&h2,   g_h2);
    cudaGetSymbolAddress((void**)&eo,   g_eo);
    cudaGetSymbolAddress((void**)&cnt,  g_cnt);
    cudaGetSymbolAddress((void**)&list, g_list);

    // --- MHLA path ---
    rmsnorm_kernel<<<TOK, 256>>>(x, r1w, y1);
    wl_gemm<<<dim3(128, SPLITK), 256>>>(y1, Wl, part);
    wl_reduce<<<TOK, 256>>>(part, bl, lat);
    gemm64<<<dim3(4, 32, 1), 256>>>(y1,  Wq, bq, nullptr, q,  TOK, DMODEL, DMODEL, nullptr, nullptr, 0, 0);
    gemm64<<<dim3(4, 32, 1), 256>>>(lat, Wk, bk, nullptr, kb, TOK, DMODEL, DMODEL, nullptr, nullptr, 0, 0);
    gemm64<<<dim3(4, 32, 1), 256>>>(lat, Wv, bv, nullptr, vb, TOK, DMODEL, DMODEL, nullptr, nullptr, 0, 0);
    attn_kernel<<<256, 64>>>(q, kb, vb, ao);
    gemm64<<<dim3(4, 32, 1), 256>>>(ao, Wo, bo, x, x2, TOK, DMODEL, DMODEL, nullptr, nullptr, 0, 0);

    // --- MoE path ---
    rmsnorm_kernel<<<TOK, 256>>>(x2, r2w, y2);
    zero_cnt_kernel<<<1, 32>>>(cnt);
    route_kernel<<<TOK, 32>>>(y2, rw, rb, topv, cnt, list);
    gemm64<<<dim3(16, 32, NEXP), 256>>>(y2, W1,  b1, nullptr, h1, 0, FEXP,   DMODEL, list, cnt, 1, 0);
    gemm64<<<dim3(16, 32, NEXP), 256>>>(h1, Wsx, bs, nullptr, h2, 0, FEXP,   FEXP,   list, cnt, 2, 1);
    gemm64<<<dim3(4,  32, NEXP), 256>>>(h2, W2,  b2, nullptr, eo, 0, DMODEL, FEXP,   list, cnt, 3, 0);
    combine_kernel<<<TOK, 256>>>(x2, topv, eo, (float*)d_out);
}

// round 2
// speedup vs baseline: 1.2241x; 1.2241x over previous
#include <cuda_runtime.h>
#include <cuda_bf16.h>
#include <cstdio>

typedef unsigned long long ull;

// B=32, S=64, D=256, H=8, E=8, K(topk)=2, F=1024, LATENT=64, HD=32
#define TOK      2048
#define DMODEL   256
#define NBIG     16384
#define SPLITK   8
#define KCHUNK   2048          // 16384/8
#define FEXP     1024
#define NEXP     8

// ---------------- scratch ----------------
__device__ float g_y1 [TOK*DMODEL];
__device__ float g_part[SPLITK*32*NBIG];
__device__ float g_lat[TOK*DMODEL];
__device__ float g_q  [TOK*DMODEL];
__device__ float g_k  [TOK*DMODEL];
__device__ float g_v  [TOK*DMODEL];
__device__ float g_ao [TOK*DMODEL];
__device__ float g_x2 [TOK*DMODEL];
__device__ float g_y2 [TOK*DMODEL];
__device__ float g_topv[TOK*2];
__device__ int   g_cnt[NEXP];
__device__ int   g_list[NEXP*TOK];
__device__ float g_h1 [NEXP*TOK*FEXP];
__device__ float g_h2 [NEXP*TOK*FEXP];
__device__ float g_eo [2*TOK*DMODEL];

// ---------------- packed fp32x2 helpers ----------------
__device__ __forceinline__ void ffma2(ull& d, ull a, ull b) {
    asm("fma.rn.f32x2 %0, %1, %2, %0;" : "+l"(d) : "l"(a), "l"(b));
}
__device__ __forceinline__ ull dup2(float x) {
    ull r; unsigned xi = __float_as_uint(x);
    asm("mov.b64 %0, {%1, %1};" : "=l"(r) : "r"(xi));
    return r;
}
__device__ __forceinline__ float2 unpack2(ull a) {
    unsigned lo, hi;
    asm("mov.b64 {%0, %1}, %2;" : "=r"(lo), "=r"(hi) : "l"(a));
    float2 r; r.x = __uint_as_float(lo); r.y = __uint_as_float(hi);
    return r;
}
__device__ __forceinline__ unsigned smem_u32(const void* p) {
    return (unsigned)__cvta_generic_to_shared(p);
}
#define CPA16(dst, src) asm volatile("cp.async.cg.shared.global [%0], [%1], 16;" :: "r"(dst), "l"(src))
#define CPA_COMMIT()    asm volatile("cp.async.commit_group;")
#define CPA_WAIT0()     asm volatile("cp.async.wait_group 0;")

// ---------------- rmsnorm ----------------
__global__ void rmsnorm_kernel(const float* __restrict__ in, const float* __restrict__ w,
                               float* __restrict__ out) {
    int row = blockIdx.x, t = threadIdx.x;
    float v = in[(size_t)row*DMODEL + t];
    float ss = v*v;
    #pragma unroll
    for (int o = 16; o > 0; o >>= 1) ss += __shfl_xor_sync(0xffffffffu, ss, o);
    __shared__ float ws[8];
    if ((t & 31) == 0) ws[t >> 5] = ss;
    __syncthreads();
    float tot = 0.f;
    #pragma unroll
    for (int i = 0; i < 8; i++) tot += ws[i];
    float sc = rsqrtf(tot * (1.0f/256.0f) + 1e-5f);
    out[(size_t)row*DMODEL + t] = v * sc * w[t];
}

// ---------------- Wl GEMM (32 x 16384 x 16384), split-K=8 ----------------
__global__ void wl_gemm(const float* __restrict__ A, const float* __restrict__ W,
                        float* __restrict__ part) {
    __shared__ __align__(16) float As[32*34];
    __shared__ __align__(16) float Bs[32*128];
    int tid = threadIdx.x;
    int n0 = blockIdx.x * 128;
    int kbase = blockIdx.y * KCHUNK;
    int ng = tid & 31, mg = tid >> 5;
    ull acc[2][4];
    #pragma unroll
    for (int i = 0; i < 2; i++)
        #pragma unroll
        for (int j = 0; j < 4; j++) acc[i][j] = 0ULL;

    for (int kt = 0; kt < KCHUNK; kt += 32) {
        __syncthreads();
        {
            int kk = tid & 31, r0 = tid >> 5;
            #pragma unroll
            for (int p = 0; p < 4; p++) {
                int r = r0 + p*8;
                As[kk*34 + r] = A[(size_t)r*NBIG + kbase + kt + kk];
            }
        }
        {
            int nn = tid & 127, kx = tid >> 7;
            #pragma unroll
            for (int p = 0; p < 16; p++) {
                int kk = kx + p*2;
                Bs[kk*128 + nn] = W[(size_t)(kbase + kt + kk)*NBIG + n0 + nn];
            }
        }
        __syncthreads();
        #pragma unroll
        for (int k = 0; k < 32; k++) {
            ull a0 = *(const ull*)&As[k*34 + mg*4];
            ull a1 = *(const ull*)&As[k*34 + mg*4 + 2];
            float4 b4 = *(const float4*)&Bs[k*128 + ng*4];
            ull b0 = dup2(b4.x), b1 = dup2(b4.y), b2 = dup2(b4.z), b3 = dup2(b4.w);
            ffma2(acc[0][0], a0, b0); ffma2(acc[0][1], a0, b1);
            ffma2(acc[0][2], a0, b2); ffma2(acc[0][3], a0, b3);
            ffma2(acc[1][0], a1, b0); ffma2(acc[1][1], a1, b1);
            ffma2(acc[1][2], a1, b2); ffma2(acc[1][3], a1, b3);
        }
    }
    size_t base = (size_t)blockIdx.y * (32*(size_t)NBIG);
    #pragma unroll
    for (int rp = 0; rp < 2; rp++) {
        #pragma unroll
        for (int c = 0; c < 4; c++) {
            float2 f = unpack2(acc[rp][c]);
            int n = n0 + ng*4 + c;
            int r = mg*4 + rp*2;
            part[base + (size_t)r*NBIG + n]     = f.x;
            part[base + (size_t)(r+1)*NBIG + n] = f.y;
        }
    }
}

__global__ void wl_reduce(const float* __restrict__ part, const float* __restrict__ bl,
                          float* __restrict__ lat) {
    int i = blockIdx.x * 256 + threadIdx.x;
    float s = bl[i & (NBIG-1)];
    #pragma unroll
    for (int p = 0; p < SPLITK; p++) s += part[(size_t)p*32*NBIG + i];
    lat[i] = s;
}

// ---------------- gemm128: BM=128 BN=128 BK=16, 256 thr, 8x8/thread via f32x2 ----
// mode 0: C[r] = A[r]@W (+bias)(+resid)
// mode 1: A gathered via list>>1 -> C at e*TOK
// mode 2: A at e*TOK -> C at e*TOK
// mode 3: A at e*TOK -> C scattered by list (slot,tok)
__global__ __launch_bounds__(256, 2)
void gemm128(const float* __restrict__ A, const float* __restrict__ W,
             const float* __restrict__ bias, const float* __restrict__ resid,
             float* __restrict__ C, int M, int N, int K,
             const int* __restrict__ list, const int* __restrict__ cntp,
             int mode, int relu) {
    __shared__ __align__(16) float As[2][16][130];
    __shared__ __align__(16) float Bs[2][16][128];
    __shared__ const float* rowp[128];

    int e = blockIdx.z;
    int rows = cntp ? cntp[e] : M;
    int m0 = blockIdx.y * 128;
    if (m0 >= rows) return;
    int n0 = blockIdx.x * 128;
    const float* We = W + (size_t)e * K * N;
    const float* be = bias + (size_t)e * N;
    int tid = threadIdx.x;
    int ty = tid & 15, tx = tid >> 4;

    if (tid < 128) {
        int r = m0 + tid;
        const float* p = nullptr;
        if (r < rows) {
            if (mode == 1)      p = A + (size_t)(list[e*TOK + r] >> 1) * K;
            else if (mode == 0) p = A + (size_t)r * K;
            else                p = A + ((size_t)e*TOK + r) * K;
        }
        rowp[tid] = p;
    }
    __syncthreads();

    int akk = tid & 15;       // A stage: k within step
    int arb = tid >> 4;       // A stage: row base
    int bf  = tid & 31;       // B stage: float4 col
    int bkk = tid >> 5;       // B stage: k row (and +8)

    ull acc[4][8];
    #pragma unroll
    for (int i = 0; i < 4; i++)
        #pragma unroll
        for (int j = 0; j < 8; j++) acc[i][j] = 0ULL;

    float aregs[8];
    int nsteps = K >> 4;

    // ---- stage helpers (inlined manually) ----
    // prologue: buffer 0
    {
        const float* s0 = We + (size_t)bkk*N + n0 + bf*4;
        const float* s1 = We + (size_t)(bkk+8)*N + n0 + bf*4;
        CPA16(smem_u32(&Bs[0][bkk][bf*4]), s0);
        CPA16(smem_u32(&Bs[0][bkk+8][bf*4]), s1);
        CPA_COMMIT();
        #pragma unroll
        for (int q = 0; q < 8; q++) {
            const float* p = rowp[arb + 16*q];
            aregs[q] = p ? p[akk] : 0.f;
        }
        #pragma unroll
        for (int q = 0; q < 8; q++) As[0][akk][arb + 16*q] = aregs[q];
        CPA_WAIT0();
        __syncthreads();
    }

    int buf = 0;
    for (int s = 0; s < nsteps; s++) {
        int k0n = (s + 1) << 4;
        bool has = (s + 1 < nsteps);
        if (has) {
            const float* s0 = We + (size_t)(k0n + bkk)*N + n0 + bf*4;
            const float* s1 = We + (size_t)(k0n + bkk + 8)*N + n0 + bf*4;
            CPA16(smem_u32(&Bs[buf^1][bkk][bf*4]), s0);
            CPA16(smem_u32(&Bs[buf^1][bkk+8][bf*4]), s1);
            CPA_COMMIT();
            #pragma unroll
            for (int q = 0; q < 8; q++) {
                const float* p = rowp[arb + 16*q];
                aregs[q] = p ? p[k0n + akk] : 0.f;
            }
        }
        // compute on buf
        #pragma unroll
        for (int kk = 0; kk < 16; kk++) {
            ull a0 = *(const ull*)&As[buf][kk][2*ty];
            ull a1 = *(const ull*)&As[buf][kk][2*ty + 32];
            ull a2 = *(const ull*)&As[buf][kk][2*ty + 64];
            ull a3 = *(const ull*)&As[buf][kk][2*ty + 96];
            float4 b4a = *(const float4*)&Bs[buf][kk][tx*8];
            float4 b4b = *(const float4*)&Bs[buf][kk][tx*8 + 4];
            ull d0 = dup2(b4a.x), d1 = dup2(b4a.y), d2 = dup2(b4a.z), d3 = dup2(b4a.w);
            ull d4 = dup2(b4b.x), d5 = dup2(b4b.y), d6 = dup2(b4b.z), d7 = dup2(b4b.w);
            ffma2(acc[0][0], a0, d0); ffma2(acc[0][1], a0, d1);
            ffma2(acc[0][2], a0, d2); ffma2(acc[0][3], a0, d3);
            ffma2(acc[0][4], a0, d4); ffma2(acc[0][5], a0, d5);
            ffma2(acc[0][6], a0, d6); ffma2(acc[0][7], a0, d7);
            ffma2(acc[1][0], a1, d0); ffma2(acc[1][1], a1, d1);
            ffma2(acc[1][2], a1, d2); ffma2(acc[1][3], a1, d3);
            ffma2(acc[1][4], a1, d4); ffma2(acc[1][5], a1, d5);
            ffma2(acc[1][6], a1, d6); ffma2(acc[1][7], a1, d7);
            ffma2(acc[2][0], a2, d0); ffma2(acc[2][1], a2, d1);
            ffma2(acc[2][2], a2, d2); ffma2(acc[2][3], a2, d3);
            ffma2(acc[2][4], a2, d4); ffma2(acc[2][5], a2, d5);
            ffma2(acc[2][6], a2, d6); ffma2(acc[2][7], a2, d7);
            ffma2(acc[3][0], a3, d0); ffma2(acc[3][1], a3, d1);
            ffma2(acc[3][2], a3, d2); ffma2(acc[3][3], a3, d3);
            ffma2(acc[3][4], a3, d4); ffma2(acc[3][5], a3, d5);
            ffma2(acc[3][6], a3, d6); ffma2(acc[3][7], a3, d7);
        }
        if (has) {
            #pragma unroll
            for (int q = 0; q < 8; q++) As[buf^1][akk][arb + 16*q] = aregs[q];
            CPA_WAIT0();
        }
        __syncthreads();
        buf ^= 1;
    }

    // epilogue
    #pragma unroll
    for (int i = 0; i < 4; i++) {
        int r = m0 + 2*ty + 32*i;
        float* c0 = nullptr; float* c1 = nullptr;
        if (r < rows) {
            if (mode == 3) {
                int ent = list[e*TOK + r];
                c0 = C + (size_t)(ent & 1)*TOK*N + (size_t)(ent >> 1)*N;
            } else if (mode == 0) c0 = C + (size_t)r*N;
            else                  c0 = C + ((size_t)e*TOK + r)*N;
        }
        if (r + 1 < rows) {
            if (mode == 3) {
                int ent = list[e*TOK + r + 1];
                c1 = C + (size_t)(ent & 1)*TOK*N + (size_t)(ent >> 1)*N;
            } else if (mode == 0) c1 = C + (size_t)(r+1)*N;
            else                  c1 = C + ((size_t)e*TOK + r + 1)*N;
        }
        #pragma unroll
        for (int j = 0; j < 8; j++) {
            float2 f = unpack2(acc[i][j]);
            int n = n0 + tx*8 + j;
            float bn = be[n];
            if (c0) {
                float v = f.x + bn;
                if (resid) v += resid[(size_t)r*N + n];
                if (relu)  v = fmaxf(v, 0.f);
                c0[n] = v;
            }
            if (c1) {
                float v = f.y + bn;
                if (resid) v += resid[(size_t)(r+1)*N + n];
                if (relu)  v = fmaxf(v, 0.f);
                c1[n] = v;
            }
        }
    }
}

// ---------------- attention ----------------
__global__ void attn_kernel(const float* __restrict__ q, const float* __restrict__ k,
                            const float* __restrict__ v, float* __restrict__ ao) {
    int bh = blockIdx.x;
    int b = bh >> 3, h = bh & 7;
    int s = threadIdx.x;
    __shared__ float ks[64][32];
    __shared__ float vs[64][32];
    for (int idx = s; idx < 2048; idx += 64) {
        int l = idx >> 5, d = idx & 31;
        size_t src = (size_t)(b*64 + l)*DMODEL + h*32 + d;
        ks[l][d] = k[src];
        vs[l][d] = v[src];
    }
    __syncthreads();

    float qr[32];
    const float* qp = q + (size_t)(b*64 + s)*DMODEL + h*32;
    #pragma unroll
    for (int d = 0; d < 32; d++) qr[d] = qp[d];

    #pragma unroll
    for (int i = 0; i < 16; i++) {
        float fr = powf(10000.0f, -(float)i / 16.0f);
        float ang = (float)s * fr;
        float c = cosf(ang), sn = sinf(ang);
        float X = qr[2*i], Y = qr[2*i + 1];
        float nX = X*c - Y*sn;
        float nY = nX*sn + Y*c;
        qr[2*i] = nX; qr[2*i + 1] = nY;
    }

    const float scale = 0.1767766952966369f;
    float sc[64];
    float mx = -1e30f;
    #pragma unroll
    for (int l = 0; l < 64; l++) {
        float p = 0.f;
        #pragma unroll
        for (int d = 0; d < 32; d++) p += qr[d] * ks[l][d];
        p *= scale;
        sc[l] = p;
        mx = fmaxf(mx, p);
    }
    float se = 0.f;
    #pragma unroll
    for (int l = 0; l < 64; l++) { sc[l] = __expf(sc[l] - mx); se += sc[l]; }
    float inv = 1.0f / se;

    float* op = ao + (size_t)(b*64 + s)*DMODEL + h*32;
    #pragma unroll
    for (int d = 0; d < 32; d++) {
        float a = 0.f;
        #pragma unroll
        for (int l = 0; l < 64; l++) a += sc[l] * vs[l][d];
        op[d] = a * inv;
    }
}

// ---------------- router ----------------
__global__ void zero_cnt_kernel(int* cnt) { if (threadIdx.x < NEXP) cnt[threadIdx.x] = 0; }

__global__ void route_kernel(const float* __restrict__ y2, const float* __restrict__ rw,
                             const float* __restrict__ rb, float* __restrict__ topv,
                             int* __restrict__ cnt, int* __restrict__ list) {
    int tok = blockIdx.x, lane = threadIdx.x;
    float xv[8];
    #pragma unroll
    for (int j = 0; j < 8; j++) xv[j] = y2[(size_t)tok*DMODEL + j*32 + lane];
    float lg[8];
    #pragma unroll
    for (int e = 0; e < 8; e++) {
        float p = 0.f;
        #pragma unroll
        for (int j = 0; j < 8; j++) p += xv[j] * rw[(j*32 + lane)*NEXP + e];
        #pragma unroll
        for (int o = 16; o > 0; o >>= 1) p += __shfl_xor_sync(0xffffffffu, p, o);
        lg[e] = p;
    }
    if (lane == 0) {
        float mx = -1e30f;
        #pragma unroll
        for (int e = 0; e < 8; e++) { lg[e] += rb[e]; mx = fmaxf(mx, lg[e]); }
        float se = 0.f, pr[8];
        #pragma unroll
        for (int e = 0; e < 8; e++) { pr[e] = __expf(lg[e] - mx); se += pr[e]; }
        float inv = 1.0f / se;
        #pragma unroll
        for (int e = 0; e < 8; e++) pr[e] *= inv;
        int b0 = 0; float v0 = -1.f;
        #pragma unroll
        for (int e = 0; e < 8; e++) if (pr[e] > v0) { v0 = pr[e]; b0 = e; }
        int b1 = -1; float v1 = -1.f;
        #pragma unroll
        for (int e = 0; e < 8; e++) if (e != b0 && pr[e] > v1) { v1 = pr[e]; b1 = e; }
        topv[tok*2 + 0] = v0;
        topv[tok*2 + 1] = v1;
        int p0 = atomicAdd(&cnt[b0], 1); list[b0*TOK + p0] = tok*2;
        int p1 = atomicAdd(&cnt[b1], 1); list[b1*TOK + p1] = tok*2 + 1;
    }
}

// ---------------- combine ----------------
__global__ void combine_kernel(const float* __restrict__ x2, const float* __restrict__ topv,
                               const float* __restrict__ eo, float* __restrict__ out) {
    int tok = blockIdx.x, d = threadIdx.x;
    size_t i = (size_t)tok*DMODEL + d;
    out[i] = x2[i] + topv[tok*2] * eo[i] + topv[tok*2 + 1] * eo[(size_t)TOK*DMODEL + i];
}

// ---------------- host ----------------
extern "C" void kernel_launch(void* const* d_in, const int* in_sizes, int n_in,
                              void* d_out, int out_size) {
    const float* x   = (const float*)d_in[0];
    const float* r1w = (const float*)d_in[1];
    const float* Wl  = (const float*)d_in[2];
    const float* bl  = (const float*)d_in[3];
    const float* Wq  = (const float*)d_in[4];
    const float* bq  = (const float*)d_in[5];
    const float* Wk  = (const float*)d_in[6];
    const float* bk  = (const float*)d_in[7];
    const float* Wv  = (const float*)d_in[8];
    const float* bv  = (const float*)d_in[9];
    const float* Wo  = (const float*)d_in[10];
    const float* bo  = (const float*)d_in[11];
    const float* r2w = (const float*)d_in[12];
    const float* rw  = (const float*)d_in[13];
    const float* rb  = (const float*)d_in[14];
    const float* W1  = (const float*)d_in[15];
    const float* b1  = (const float*)d_in[16];
    const float* Wsx = (const float*)d_in[17];
    const float* bs  = (const float*)d_in[18];
    const float* W2  = (const float*)d_in[19];
    const float* b2  = (const float*)d_in[20];

    float *y1, *part, *lat, *q, *kb, *vb, *ao, *x2, *y2, *topv, *h1, *h2, *eo;
    int *cnt, *list;
    cudaGetSymbolAddress((void**)&y1,   g_y1);
    cudaGetSymbolAddress((void**)&part, g_part);
    cudaGetSymbolAddress((void**)&lat,  g_lat);
    cudaGetSymbolAddress((void**)&q,    g_q);
    cudaGetSymbolAddress((void**)&kb,   g_k);
    cudaGetSymbolAddress((void**)&vb,   g_v);
    cudaGetSymbolAddress((void**)&ao,   g_ao);
    cudaGetSymbolAddress((void**)&x2,   g_x2);
    cudaGetSymbolAddress((void**)&y2,   g_y2);
    cudaGetSymbolAddress((void**)&topv, g_topv);
    cudaGetSymbolAddress((void**)&h1,   g_h1);
    cudaGetSymbolAddress((void**)&h2,   g_h2);
    cudaGetSymbolAddress((void**)&eo,   g_eo);
    cudaGetSymbolAddress((void**)&cnt,  g_cnt);
    cudaGetSymbolAddress((void**)&list, g_list);

    // --- MHLA ---
    rmsnorm_kernel<<<TOK, 256>>>(x, r1w, y1);
    wl_gemm<<<dim3(128, SPLITK), 256>>>(y1, Wl, part);
    wl_reduce<<<TOK, 256>>>(part, bl, lat);
    gemm128<<<dim3(2, 16, 1), 256>>>(y1,  Wq, bq, nullptr, q,  TOK, DMODEL, DMODEL, nullptr, nullptr, 0, 0);
    gemm128<<<dim3(2, 16, 1), 256>>>(lat, Wk, bk, nullptr, kb, TOK, DMODEL, DMODEL, nullptr, nullptr, 0, 0);
    gemm128<<<dim3(2, 16, 1), 256>>>(lat, Wv, bv, nullptr, vb, TOK, DMODEL, DMODEL, nullptr, nullptr, 0, 0);
    attn_kernel<<<256, 64>>>(q, kb, vb, ao);
    gemm128<<<dim3(2, 16, 1), 256>>>(ao, Wo, bo, x, x2, TOK, DMODEL, DMODEL, nullptr, nullptr, 0, 0);

    // --- MoE ---
    rmsnorm_kernel<<<TOK, 256>>>(x2, r2w, y2);
    zero_cnt_kernel<<<1, 32>>>(cnt);
    route_kernel<<<TOK, 32>>>(y2, rw, rb, topv, cnt, list);
    gemm128<<<dim3(8, 16, NEXP), 256>>>(y2, W1,  b1, nullptr, h1, 0, FEXP,   DMODEL, list, cnt, 1, 0);
    gemm128<<<dim3(8, 16, NEXP), 256>>>(h1, Wsx, bs, nullptr, h2, 0, FEXP,   FEXP,   list, cnt, 2, 1);
    gemm128<<<dim3(2, 16, NEXP), 256>>>(h2, W2,  b2, nullptr, eo, 0, DMODEL, FEXP,   list, cnt, 3, 0);
    combine_kernel<<<TOK, 256>>>(x2, topv, eo, (float*)d_out);
}